// round 7
// baseline (speedup 1.0000x reference)
#include <cuda_runtime.h>
#include <cuda_bf16.h>

// Single-pass fused blocked-scan RK4 on a 4-state LTI system.
// x_{t+1} = Phi x_t + Gam u_t (exact RK4 algebra for linear ODE + ZOH input).
//   k_init : 16-thread double build of Phi, Gam, M[s]=Phi^(L*2^s) s=0..17; zero flags
//   k_main : one kernel, chains of L=8 steps held in registers:
//            phase1 (offsets from 0) -> block Kogge-Stone scan -> publish aggregate
//            -> wait+fold previous block aggregates -> per-thread start via binary
//            matrix-power product -> phase2 rerun from registers, emit (z1, z2).

#define LSTEP 8
#define BLK 1024
#define MAXB 512

__device__ float g_fPhi[16];
__device__ float g_fGam[8];
__device__ float g_fM[18][16];        // M[s] = Phi^(LSTEP * 2^s)
__device__ float4 g_agg[MAXB];
__device__ int g_flag[MAXB];

__global__ void k_init(const float* c, const float* m, const float* k,
                       const float* dtp) {
    __shared__ double sA[16], sP[16], sT[16], sR[16];
    int t = threadIdx.x;           // 16 threads
    int r = t >> 2, col = t & 3;

    for (int i = t; i < MAXB; i += 16) g_flag[i] = 0;

    double c1 = c[0], c2 = c[1], c3 = c[2];
    double m1 = m[0], m2 = m[1];
    double k1 = k[0], k2 = k[1], k3 = k[2];
    double h = dtp[0];

    if (t == 0) {
        sA[0] = 0.0;  sA[1] = 1.0;  sA[2] = 0.0;  sA[3] = 0.0;
        sA[4] = -(k1 + k2) / m1; sA[5] = -(c1 + c2) / m1; sA[6] = k2 / m1; sA[7] = c2 / m1;
        sA[8] = 0.0;  sA[9] = 0.0;  sA[10] = 0.0; sA[11] = 1.0;
        sA[12] = k2 / m2; sA[13] = c2 / m2; sA[14] = -(k3 + k2) / m2; sA[15] = -(c3 + c2) / m2;
    }
    __syncwarp(0xffffu);

    double id = (r == col) ? 1.0 : 0.0;
    double h2 = h * h, h3 = h2 * h, h4 = h3 * h;
    double ph = id + h * sA[t];                 // Phi accumulator
    double g4 = h * id + (h2 / 2.0) * sA[t];    // G4 accumulator
    sP[t] = sA[t];
    __syncwarp(0xffffu);

    double coefP[3] = { h2 / 2.0, h3 / 6.0, h4 / 24.0 };
    double coefG[2] = { h3 / 6.0, h4 / 24.0 };
    for (int q = 0; q < 3; q++) {               // A^2, A^3, A^4
        double s = 0.0;
        for (int kk = 0; kk < 4; kk++) s += sP[r * 4 + kk] * sA[kk * 4 + col];
        __syncwarp(0xffffu);
        sP[t] = s;
        __syncwarp(0xffffu);
        ph += coefP[q] * s;
        if (q < 2) g4 += coefG[q] * s;
    }

    g_fPhi[t] = (float)ph;
    sT[t] = g4;
    __syncwarp(0xffffu);
    if (t < 8) {   // Gam = G4 * B with B[1][0]=1/m1, B[3][1]=1/m2
        int rr = t >> 1, cc = t & 1;
        g_fGam[t] = (float)(sT[rr * 4 + (cc ? 3 : 1)] / (cc ? m2 : m1));
    }

    // sR = Phi^LSTEP (LSTEP=8 -> 3 squarings of Phi)
    sR[t] = ph;
    __syncwarp(0xffffu);
    for (int q = 0; q < 3; q++) {
        double s = 0.0;
        for (int kk = 0; kk < 4; kk++) s += sR[r * 4 + kk] * sR[kk * 4 + col];
        __syncwarp(0xffffu);
        sR[t] = s;
        __syncwarp(0xffffu);
    }
    g_fM[0][t] = (float)sR[t];
    for (int ms = 1; ms < 18; ms++) {           // successive squarings
        double s = 0.0;
        for (int kk = 0; kk < 4; kk++) s += sR[r * 4 + kk] * sR[kk * 4 + col];
        __syncwarp(0xffffu);
        sR[t] = s;
        __syncwarp(0xffffu);
        g_fM[ms][t] = (float)sR[t];
    }
}

#define STEP(ua, ub)                                                                         \
    do {                                                                                     \
        float n0 = fmaf(P[3],  x3, fmaf(P[2],  x2, fmaf(P[1],  x1, fmaf(P[0],  x0,          \
                   fmaf(G[1], (ub), G[0] * (ua))))));                                        \
        float n1 = fmaf(P[7],  x3, fmaf(P[6],  x2, fmaf(P[5],  x1, fmaf(P[4],  x0,          \
                   fmaf(G[3], (ub), G[2] * (ua))))));                                        \
        float n2 = fmaf(P[11], x3, fmaf(P[10], x2, fmaf(P[9],  x1, fmaf(P[8],  x0,          \
                   fmaf(G[5], (ub), G[4] * (ua))))));                                        \
        float n3 = fmaf(P[15], x3, fmaf(P[14], x2, fmaf(P[13], x1, fmaf(P[12], x0,          \
                   fmaf(G[7], (ub), G[6] * (ua))))));                                        \
        x0 = n0; x1 = n1; x2 = n2; x3 = n3;                                                  \
    } while (0)

// _v = M*_w + _v   (float4s; param names collision-free vs field names)
#define AFF(Mm, _v, _w)                                                                      \
    do {                                                                                     \
        float n0 = fmaf(Mm[0],  (_w).x, fmaf(Mm[1],  (_w).y, fmaf(Mm[2],  (_w).z, fmaf(Mm[3],  (_w).w, (_v).x)))); \
        float n1 = fmaf(Mm[4],  (_w).x, fmaf(Mm[5],  (_w).y, fmaf(Mm[6],  (_w).z, fmaf(Mm[7],  (_w).w, (_v).y)))); \
        float n2 = fmaf(Mm[8],  (_w).x, fmaf(Mm[9],  (_w).y, fmaf(Mm[10], (_w).z, fmaf(Mm[11], (_w).w, (_v).z)))); \
        float n3 = fmaf(Mm[12], (_w).x, fmaf(Mm[13], (_w).y, fmaf(Mm[14], (_w).z, fmaf(Mm[15], (_w).w, (_v).w)))); \
        (_v).x = n0; (_v).y = n1; (_v).z = n2; (_v).w = n3;                                  \
    } while (0)

// _w = M*_w
#define MATP(Mm, _w)                                                                         \
    do {                                                                                     \
        float n0 = fmaf(Mm[0],  (_w).x, fmaf(Mm[1],  (_w).y, fmaf(Mm[2],  (_w).z, Mm[3]  * (_w).w))); \
        float n1 = fmaf(Mm[4],  (_w).x, fmaf(Mm[5],  (_w).y, fmaf(Mm[6],  (_w).z, Mm[7]  * (_w).w))); \
        float n2 = fmaf(Mm[8],  (_w).x, fmaf(Mm[9],  (_w).y, fmaf(Mm[10], (_w).z, Mm[11] * (_w).w))); \
        float n3 = fmaf(Mm[12], (_w).x, fmaf(Mm[13], (_w).y, fmaf(Mm[14], (_w).z, Mm[15] * (_w).w))); \
        (_w).x = n0; (_w).y = n1; (_w).z = n2; (_w).w = n3;                                  \
    } while (0)

__global__ void __launch_bounds__(BLK) k_main(const float* __restrict__ u,
                                              const float* __restrict__ x0in,
                                              float* __restrict__ out, int T) {
    __shared__ float sM[18][16];
    __shared__ float4 V[BLK];
    __shared__ float4 sAgg[MAXB];
    __shared__ float4 sF[4];
    __shared__ int sLen[4];
    __shared__ float4 sPref;

    int tid = threadIdx.x;
    int b = blockIdx.x;
    int p = b * BLK + tid;

    if (tid < 288) ((float*)sM)[tid] = ((const float*)g_fM)[tid];

    float P[16], G[8];
#pragma unroll
    for (int i = 0; i < 16; i++) P[i] = g_fPhi[i];
#pragma unroll
    for (int i = 0; i < 8; i++) G[i] = g_fGam[i];

    int t0 = p * LSTEP;
    int te = t0 + LSTEP; if (te > T) te = T;
    int rem = te - t0;  if (rem < 0) rem = 0;     // steps this thread owns (0..8)

    // ---- load u into registers (guarded) ----
    float4 a[4];
#pragma unroll
    for (int j = 0; j < 4; j++) {
        a[j] = make_float4(0.f, 0.f, 0.f, 0.f);
        int base = 2 * j;                          // step offset within chain
        if (base + 2 <= rem)      a[j] = *(const float4*)(u + 2 * (t0 + base));
        else if (base + 1 <= rem) { float2 h2 = *(const float2*)(u + 2 * (t0 + base));
                                    a[j].x = h2.x; a[j].y = h2.y; }
    }

    // ---- phase 1: run chain from 0 (global chain 0 from x0) ----
    float x0 = 0.f, x1 = 0.f, x2 = 0.f, x3 = 0.f;
    if (p == 0) { x0 = x0in[0]; x1 = x0in[1]; x2 = x0in[2]; x3 = x0in[3]; }
#pragma unroll
    for (int j = 0; j < 4; j++) {
        int base = 2 * j;
        if (base + 1 <= rem) STEP(a[j].x, a[j].y);
        if (base + 2 <= rem) STEP(a[j].z, a[j].w);
    }

    // ---- block Kogge-Stone scan (constant-matrix trick) ----
    float4 v = make_float4(x0, x1, x2, x3);
    V[tid] = v;
    __syncthreads();
#pragma unroll
    for (int s = 0; s < 10; s++) {
        int d = 1 << s;
        float4 w;
        bool act = (tid >= d);
        if (act) w = V[tid - d];
        __syncthreads();
        if (act) {
            const float* M = sM[s];
            AFF(M, v, w);
            V[tid] = v;
        }
        __syncthreads();
    }

    // ---- publish aggregate ----
    if (tid == BLK - 1) {
        g_agg[b] = v;
        __threadfence();
        atomicExch(&g_flag[b], 1);
    }

    // ---- wait for + load previous aggregates ----
    if (tid < b) {
        while (atomicAdd(&g_flag[tid], 0) == 0) { }
        __threadfence();
        sAgg[tid] = g_agg[tid];
    }
    __syncthreads();

    // ---- 4-way parallel fold: Pref_b = sum_{j<b} MB^{b-1-j} * S_j,  MB = Phi^(BLK*LSTEP) ----
    const float* MB = sM[10];
    if (tid < 4) {
        int q = (b + 3) >> 2;
        int j0 = tid * q, j1 = j0 + q; if (j1 > b) j1 = b; if (j0 > b) j0 = b;
        float4 F = make_float4(0.f, 0.f, 0.f, 0.f);
        for (int j = j0; j < j1; j++) {
            float4 S = sAgg[j];
            MATP(MB, F);
            F.x += S.x; F.y += S.y; F.z += S.z; F.w += S.w;
        }
        sF[tid] = F; sLen[tid] = j1 - j0;
    }
    __syncthreads();
    if (tid == 0) {
        float4 acc = (b > 0) ? sF[0] : make_float4(0.f, 0.f, 0.f, 0.f);
#pragma unroll
        for (int l = 1; l < 4; l++) {
            int r = sLen[l];
#pragma unroll
            for (int s = 0; s < 8; s++)
                if ((r >> s) & 1) { const float* M = sM[10 + s]; MATP(M, acc); }
            float4 F = sF[l];
            acc.x += F.x; acc.y += F.y; acc.z += F.z; acc.w += F.w;
        }
        sPref = acc;
    }
    __syncthreads();

    if (t0 >= T) return;   // all barriers done; idle tail threads exit

    // ---- per-thread start: Phi^{tid*LSTEP} * Pref_b + in-block exclusive scan ----
    if (p == 0) {
        x0 = x0in[0]; x1 = x0in[1]; x2 = x0in[2]; x3 = x0in[3];
    } else {
        float4 w = make_float4(0.f, 0.f, 0.f, 0.f);
        if (b > 0) {
            w = sPref;
#pragma unroll
            for (int s = 0; s < 10; s++)
                if ((tid >> s) & 1) { const float* M = sM[s]; MATP(M, w); }
        }
        if (tid > 0) {
            float4 sc = V[tid - 1];
            w.x += sc.x; w.y += sc.y; w.z += sc.z; w.w += sc.w;
        }
        x0 = w.x; x1 = w.y; x2 = w.z; x3 = w.w;
    }

    // ---- phase 2: rerun from registers, emit (z1, z2) per step ----
    if (rem == LSTEP) {
        float4* o4 = (float4*)(out + 2 * t0);
#pragma unroll
        for (int j = 0; j < 4; j++) {
            STEP(a[j].x, a[j].y); float p0 = x0, q0 = x2;
            STEP(a[j].z, a[j].w);
            o4[j] = make_float4(p0, q0, x0, x2);
        }
    } else {
#pragma unroll
        for (int j = 0; j < 4; j++) {
            int base = 2 * j;
            if (base + 1 <= rem) {
                STEP(a[j].x, a[j].y);
                float p0 = x0, q0 = x2;
                if (base + 2 <= rem) {
                    STEP(a[j].z, a[j].w);
                    *(float4*)(out + 2 * (t0 + base)) = make_float4(p0, q0, x0, x2);
                } else {
                    *(float2*)(out + 2 * (t0 + base)) = make_float2(p0, q0);
                }
            }
        }
    }
}

extern "C" void kernel_launch(void* const* d_in, const int* in_sizes, int n_in,
                              void* d_out, int out_size) {
    const float* u  = (const float*)d_in[0];
    const float* x0 = (const float*)d_in[1];
    const float* c  = (const float*)d_in[2];
    const float* m  = (const float*)d_in[3];
    const float* k  = (const float*)d_in[4];
    const float* dt = (const float*)d_in[5];
    float* out = (float*)d_out;

    int T = in_sizes[0] / 2;
    int chains = (T + LSTEP - 1) / LSTEP;
    int grid = (chains + BLK - 1) / BLK;          // 245 for T = 2e6; <= MAXB

    k_init<<<1, 16>>>(c, m, k, dt);
    k_main<<<grid, BLK>>>(u, x0, out, T);
}

// round 8
// speedup vs baseline: 1.1421x; 1.1421x over previous
#include <cuda_runtime.h>
#include <cuda_bf16.h>

// Single-pass fused blocked-scan RK4 on a 4-state LTI system, single-wave grid.
// x_{t+1} = Phi x_t + Gam u_t (exact RK4 algebra for linear ODE + ZOH input).
//   k_init : 16-thread double build of Phi, Gam, M[s]=Phi^(16*2^s) s=0..17; zero flags
//   k_main : grid of <=148 co-resident blocks, chains of 16 steps/thread:
//            phase1 (offsets from 0) -> warp shuffle scan + warp-agg scan ->
//            publish aggregate -> decoupled-lookback fold -> per-thread start via
//            binary matrix powers -> phase2 re-run (u re-read hits L2), emit (z1,z2).

#define LSTEP 16
#define BLK 1024
#define MAXB 256

__device__ float g_fPhi[16];
__device__ float g_fGam[8];
__device__ float g_fM[18][16];        // M[s] = Phi^(LSTEP * 2^s)
__device__ float4 g_agg[MAXB];
__device__ int g_flag[MAXB];

__global__ void k_init(const float* c, const float* m, const float* k,
                       const float* dtp) {
    __shared__ double sA[16], sP[16], sT[16], sR[16];
    int t = threadIdx.x;           // 16 threads
    int r = t >> 2, col = t & 3;

    for (int i = t; i < MAXB; i += 16) g_flag[i] = 0;

    double c1 = c[0], c2 = c[1], c3 = c[2];
    double m1 = m[0], m2 = m[1];
    double k1 = k[0], k2 = k[1], k3 = k[2];
    double h = dtp[0];

    if (t == 0) {
        sA[0] = 0.0;  sA[1] = 1.0;  sA[2] = 0.0;  sA[3] = 0.0;
        sA[4] = -(k1 + k2) / m1; sA[5] = -(c1 + c2) / m1; sA[6] = k2 / m1; sA[7] = c2 / m1;
        sA[8] = 0.0;  sA[9] = 0.0;  sA[10] = 0.0; sA[11] = 1.0;
        sA[12] = k2 / m2; sA[13] = c2 / m2; sA[14] = -(k3 + k2) / m2; sA[15] = -(c3 + c2) / m2;
    }
    __syncwarp(0xffffu);

    double id = (r == col) ? 1.0 : 0.0;
    double h2 = h * h, h3 = h2 * h, h4 = h3 * h;
    double ph = id + h * sA[t];                 // Phi accumulator
    double g4 = h * id + (h2 / 2.0) * sA[t];    // G4 accumulator
    sP[t] = sA[t];
    __syncwarp(0xffffu);

    double coefP[3] = { h2 / 2.0, h3 / 6.0, h4 / 24.0 };
    double coefG[2] = { h3 / 6.0, h4 / 24.0 };
    for (int q = 0; q < 3; q++) {               // A^2, A^3, A^4
        double s = 0.0;
        for (int kk = 0; kk < 4; kk++) s += sP[r * 4 + kk] * sA[kk * 4 + col];
        __syncwarp(0xffffu);
        sP[t] = s;
        __syncwarp(0xffffu);
        ph += coefP[q] * s;
        if (q < 2) g4 += coefG[q] * s;
    }

    g_fPhi[t] = (float)ph;
    sT[t] = g4;
    __syncwarp(0xffffu);
    if (t < 8) {   // Gam = G4 * B with B[1][0]=1/m1, B[3][1]=1/m2
        int rr = t >> 1, cc = t & 1;
        g_fGam[t] = (float)(sT[rr * 4 + (cc ? 3 : 1)] / (cc ? m2 : m1));
    }

    // sR = Phi^LSTEP (LSTEP=16 -> 4 squarings of Phi)
    sR[t] = ph;
    __syncwarp(0xffffu);
    for (int q = 0; q < 4; q++) {
        double s = 0.0;
        for (int kk = 0; kk < 4; kk++) s += sR[r * 4 + kk] * sR[kk * 4 + col];
        __syncwarp(0xffffu);
        sR[t] = s;
        __syncwarp(0xffffu);
    }
    g_fM[0][t] = (float)sR[t];
    for (int ms = 1; ms < 18; ms++) {           // successive squarings
        double s = 0.0;
        for (int kk = 0; kk < 4; kk++) s += sR[r * 4 + kk] * sR[kk * 4 + col];
        __syncwarp(0xffffu);
        sR[t] = s;
        __syncwarp(0xffffu);
        g_fM[ms][t] = (float)sR[t];
    }
}

#define STEP(ua, ub)                                                                         \
    do {                                                                                     \
        float n0 = fmaf(P[3],  x3, fmaf(P[2],  x2, fmaf(P[1],  x1, fmaf(P[0],  x0,          \
                   fmaf(G[1], (ub), G[0] * (ua))))));                                        \
        float n1 = fmaf(P[7],  x3, fmaf(P[6],  x2, fmaf(P[5],  x1, fmaf(P[4],  x0,          \
                   fmaf(G[3], (ub), G[2] * (ua))))));                                        \
        float n2 = fmaf(P[11], x3, fmaf(P[10], x2, fmaf(P[9],  x1, fmaf(P[8],  x0,          \
                   fmaf(G[5], (ub), G[4] * (ua))))));                                        \
        float n3 = fmaf(P[15], x3, fmaf(P[14], x2, fmaf(P[13], x1, fmaf(P[12], x0,          \
                   fmaf(G[7], (ub), G[6] * (ua))))));                                        \
        x0 = n0; x1 = n1; x2 = n2; x3 = n3;                                                  \
    } while (0)

// _v = M*_w + _v
#define AFF(Mm, _v, _w)                                                                      \
    do {                                                                                     \
        float n0 = fmaf(Mm[0],  (_w).x, fmaf(Mm[1],  (_w).y, fmaf(Mm[2],  (_w).z, fmaf(Mm[3],  (_w).w, (_v).x)))); \
        float n1 = fmaf(Mm[4],  (_w).x, fmaf(Mm[5],  (_w).y, fmaf(Mm[6],  (_w).z, fmaf(Mm[7],  (_w).w, (_v).y)))); \
        float n2 = fmaf(Mm[8],  (_w).x, fmaf(Mm[9],  (_w).y, fmaf(Mm[10], (_w).z, fmaf(Mm[11], (_w).w, (_v).z)))); \
        float n3 = fmaf(Mm[12], (_w).x, fmaf(Mm[13], (_w).y, fmaf(Mm[14], (_w).z, fmaf(Mm[15], (_w).w, (_v).w)))); \
        (_v).x = n0; (_v).y = n1; (_v).z = n2; (_v).w = n3;                                  \
    } while (0)

// _w = M*_w
#define MATP(Mm, _w)                                                                         \
    do {                                                                                     \
        float n0 = fmaf(Mm[0],  (_w).x, fmaf(Mm[1],  (_w).y, fmaf(Mm[2],  (_w).z, Mm[3]  * (_w).w))); \
        float n1 = fmaf(Mm[4],  (_w).x, fmaf(Mm[5],  (_w).y, fmaf(Mm[6],  (_w).z, Mm[7]  * (_w).w))); \
        float n2 = fmaf(Mm[8],  (_w).x, fmaf(Mm[9],  (_w).y, fmaf(Mm[10], (_w).z, Mm[11] * (_w).w))); \
        float n3 = fmaf(Mm[12], (_w).x, fmaf(Mm[13], (_w).y, fmaf(Mm[14], (_w).z, Mm[15] * (_w).w))); \
        (_w).x = n0; (_w).y = n1; (_w).z = n2; (_w).w = n3;                                  \
    } while (0)

#define SHFL_UP4(_d, _v, _w)                                                                 \
    do {                                                                                     \
        (_w).x = __shfl_up_sync(0xffffffffu, (_v).x, (_d));                                  \
        (_w).y = __shfl_up_sync(0xffffffffu, (_v).y, (_d));                                  \
        (_w).z = __shfl_up_sync(0xffffffffu, (_v).z, (_d));                                  \
        (_w).w = __shfl_up_sync(0xffffffffu, (_v).w, (_d));                                  \
    } while (0)

__global__ void __launch_bounds__(BLK) k_main(const float* __restrict__ u,
                                              const float* __restrict__ x0in,
                                              float* __restrict__ out, int T) {
    __shared__ float sM[18][16];
    __shared__ float4 sWagg[32];
    __shared__ float4 sWscan[32];
    __shared__ float4 sAgg[MAXB];
    __shared__ float4 sF[4];
    __shared__ int sLen[4];
    __shared__ float4 sPref;

    int tid = threadIdx.x;
    int lane = tid & 31, wrp = tid >> 5;
    int b = blockIdx.x;
    int p = b * BLK + tid;

    if (tid < 288) ((float*)sM)[tid] = ((const float*)g_fM)[tid];

    float P[16], G[8];
#pragma unroll
    for (int i = 0; i < 16; i++) P[i] = g_fPhi[i];
#pragma unroll
    for (int i = 0; i < 8; i++) G[i] = g_fGam[i];
    __syncthreads();                               // sM ready

    int t0 = p * LSTEP;
    int te = t0 + LSTEP; if (te > T) te = T;
    int rem = te - t0; if (rem < 0) rem = 0;       // steps this thread owns (0..16)

    // ---- phase 1: run chain from 0 (global chain 0 from x0) ----
    float x0 = 0.f, x1 = 0.f, x2 = 0.f, x3 = 0.f;
    if (p == 0) { x0 = x0in[0]; x1 = x0in[1]; x2 = x0in[2]; x3 = x0in[3]; }
    const float4* u4 = (const float4*)(u + 2 * t0);
    if (rem == LSTEP) {
#pragma unroll
        for (int j = 0; j < LSTEP / 2; j++) {
            float4 a = u4[j];
            STEP(a.x, a.y); STEP(a.z, a.w);
        }
    } else if (rem > 0) {
        int j = 0;
        for (; 2 * (j + 1) <= rem; j++) {
            float4 a = u4[j];
            STEP(a.x, a.y); STEP(a.z, a.w);
        }
        if (2 * j < rem) {
            float2 hh = *(const float2*)(u + 2 * (t0 + 2 * j));
            STEP(hh.x, hh.y);
        }
    }

    // ---- warp Kogge-Stone scan (shuffles; M[0..4]) ----
    float4 v = make_float4(x0, x1, x2, x3);
#pragma unroll
    for (int s = 0; s < 5; s++) {
        int d = 1 << s;
        float4 w;
        SHFL_UP4(d, v, w);
        if (lane >= d) { const float* M = sM[s]; AFF(M, v, w); }
    }
    float4 ev;                                     // exclusive within-warp scan
    SHFL_UP4(1, v, ev);
    if (lane == 0) ev = make_float4(0.f, 0.f, 0.f, 0.f);
    if (lane == 31) sWagg[wrp] = v;
    __syncthreads();

    // ---- warp 0 scans the 32 warp aggregates (M[5..9]) ----
    if (wrp == 0) {
        float4 av = sWagg[lane];
#pragma unroll
        for (int s = 0; s < 5; s++) {
            int d = 1 << s;
            float4 w;
            SHFL_UP4(d, av, w);
            if (lane >= d) { const float* M = sM[5 + s]; AFF(M, av, w); }
        }
        sWscan[lane] = av;
    }
    __syncthreads();

    // ---- publish block aggregate ----
    if (tid == 0) {
        g_agg[b] = sWscan[31];
        __threadfence();
        atomicExch(&g_flag[b], 1);
    }

    // ---- decoupled lookback: wait for + load previous aggregates ----
    if (tid < b) {
        while (atomicAdd(&g_flag[tid], 0) == 0) { }
        __threadfence();
        sAgg[tid] = g_agg[tid];
    }
    __syncthreads();

    // ---- 4-way parallel fold: Pref_b = sum_{j<b} MB^{b-1-j} S_j, MB = M[10] ----
    const float* MB = sM[10];
    if (tid < 4) {
        int q = (b + 3) >> 2;
        int j0 = tid * q, j1 = j0 + q; if (j1 > b) j1 = b; if (j0 > b) j0 = b;
        float4 F = make_float4(0.f, 0.f, 0.f, 0.f);
        for (int j = j0; j < j1; j++) {
            float4 S = sAgg[j];
            MATP(MB, F);
            F.x += S.x; F.y += S.y; F.z += S.z; F.w += S.w;
        }
        sF[tid] = F; sLen[tid] = j1 - j0;
    }
    __syncthreads();
    if (tid == 0) {
        float4 acc = (b > 0) ? sF[0] : make_float4(0.f, 0.f, 0.f, 0.f);
#pragma unroll
        for (int l = 1; l < 4; l++) {
            int r = sLen[l];
#pragma unroll
            for (int s = 0; s < 7; s++)
                if ((r >> s) & 1) { const float* M = sM[10 + s]; MATP(M, acc); }
            float4 F = sF[l];
            acc.x += F.x; acc.y += F.y; acc.z += F.z; acc.w += F.w;
        }
        sPref = acc;
    }
    __syncthreads();

    if (t0 >= T) return;   // all barriers done; idle tail threads exit

    // ---- per-thread start:
    //      Phi^{16 tid} * Pref_b + Phi^{16 lane} * Wscan[wrp-1] + ev ----
    if (p == 0) {
        x0 = x0in[0]; x1 = x0in[1]; x2 = x0in[2]; x3 = x0in[3];
    } else {
        float4 sv = make_float4(0.f, 0.f, 0.f, 0.f);
        if (b > 0) {
            sv = sPref;
#pragma unroll
            for (int s = 0; s < 10; s++)
                if ((tid >> s) & 1) { const float* M = sM[s]; MATP(M, sv); }
        }
        if (wrp > 0) {
            float4 wp = sWscan[wrp - 1];
#pragma unroll
            for (int s = 0; s < 5; s++)
                if ((lane >> s) & 1) { const float* M = sM[s]; MATP(M, wp); }
            sv.x += wp.x; sv.y += wp.y; sv.z += wp.z; sv.w += wp.w;
        }
        sv.x += ev.x; sv.y += ev.y; sv.z += ev.z; sv.w += ev.w;
        x0 = sv.x; x1 = sv.y; x2 = sv.z; x3 = sv.w;
    }

    // ---- phase 2: re-run chain (u re-read: L2 hit), emit (z1, z2) per step ----
    if (rem == LSTEP) {
        float4* o4 = (float4*)(out + 2 * t0);
#pragma unroll
        for (int j = 0; j < LSTEP / 2; j++) {
            float4 a = u4[j];
            STEP(a.x, a.y); float p0 = x0, q0 = x2;
            STEP(a.z, a.w);
            o4[j] = make_float4(p0, q0, x0, x2);
        }
    } else {
        int j = 0;
        for (; 2 * (j + 1) <= rem; j++) {
            float4 a = u4[j];
            STEP(a.x, a.y); float p0 = x0, q0 = x2;
            STEP(a.z, a.w);
            *(float4*)(out + 2 * (t0 + 2 * j)) = make_float4(p0, q0, x0, x2);
        }
        if (2 * j < rem) {
            float2 hh = *(const float2*)(u + 2 * (t0 + 2 * j));
            STEP(hh.x, hh.y);
            *(float2*)(out + 2 * (t0 + 2 * j)) = make_float2(x0, x2);
        }
    }
}

extern "C" void kernel_launch(void* const* d_in, const int* in_sizes, int n_in,
                              void* d_out, int out_size) {
    const float* u  = (const float*)d_in[0];
    const float* x0 = (const float*)d_in[1];
    const float* c  = (const float*)d_in[2];
    const float* m  = (const float*)d_in[3];
    const float* k  = (const float*)d_in[4];
    const float* dt = (const float*)d_in[5];
    float* out = (float*)d_out;

    int T = in_sizes[0] / 2;
    int chains = (T + LSTEP - 1) / LSTEP;
    int grid = (chains + BLK - 1) / BLK;     // 123 for T = 2e6 -> single wave

    k_init<<<1, 16>>>(c, m, k, dt);
    k_main<<<grid, BLK>>>(u, x0, out, T);
}